// round 5
// baseline (speedup 1.0000x reference)
#include <cuda_runtime.h>
#include <cstdint>

#define B 8
#define T 1024
#define E 128
#define H 8
#define HB (H*B)
#define SCALE 0.08838834764831845f   // 1/sqrt(128)
#define NEGV (-1e9f)
#define QT 16
#define CH 128
#define KS 132                        // padded K row stride (floats)
#define THR 512

// ---------------- scratch (static device globals; no allocs allowed) --------
__device__ float g_q[HB * T * E];
__device__ float g_k[HB * T * E];
__device__ float g_v[HB * T * E];
__device__ float g_sel[B * H];

// ---------------- projection GEMM (unchanged, 172us) ------------------------
__global__ void __launch_bounds__(256) proj_kernel(const float* __restrict__ x,
                                                   const float* __restrict__ wq,
                                                   const float* __restrict__ wk,
                                                   const float* __restrict__ wv) {
    const float* w;
    float* out;
    if (blockIdx.z == 0)      { w = wq; out = g_q; }
    else if (blockIdx.z == 1) { w = wk; out = g_k; }
    else                      { w = wv; out = g_v; }

    __shared__ float xs[64][68];
    __shared__ float ws[64][68];

    const int tid = threadIdx.x;
    const int m0 = blockIdx.y * 64;
    const int n0 = blockIdx.x * 64;
    const int ty = tid >> 4;
    const int tx = tid & 15;

    float acc[4][4];
    #pragma unroll
    for (int r = 0; r < 4; r++)
        #pragma unroll
        for (int c = 0; c < 4; c++) acc[r][c] = 0.f;

    for (int k0 = 0; k0 < 128; k0 += 64) {
        #pragma unroll
        for (int i = tid; i < 1024; i += 256) {
            int row = i >> 4, c4 = i & 15;
            *(float4*)&xs[row][c4 * 4] =
                *(const float4*)(x + (size_t)(m0 + row) * 128 + k0 + c4 * 4);
        }
        #pragma unroll
        for (int i = tid; i < 1024; i += 256) {
            int row = i >> 4, c4 = i & 15;
            *(float4*)&ws[row][c4 * 4] =
                *(const float4*)(w + (size_t)(k0 + row) * 1024 + n0 + c4 * 4);
        }
        __syncthreads();
        #pragma unroll
        for (int kk = 0; kk < 64; kk++) {
            float a0 = xs[ty * 4 + 0][kk];
            float a1 = xs[ty * 4 + 1][kk];
            float a2 = xs[ty * 4 + 2][kk];
            float a3 = xs[ty * 4 + 3][kk];
            float4 b4 = *(float4*)&ws[kk][tx * 4];
            acc[0][0] = fmaf(a0, b4.x, acc[0][0]);
            acc[0][1] = fmaf(a0, b4.y, acc[0][1]);
            acc[0][2] = fmaf(a0, b4.z, acc[0][2]);
            acc[0][3] = fmaf(a0, b4.w, acc[0][3]);
            acc[1][0] = fmaf(a1, b4.x, acc[1][0]);
            acc[1][1] = fmaf(a1, b4.y, acc[1][1]);
            acc[1][2] = fmaf(a1, b4.z, acc[1][2]);
            acc[1][3] = fmaf(a1, b4.w, acc[1][3]);
            acc[2][0] = fmaf(a2, b4.x, acc[2][0]);
            acc[2][1] = fmaf(a2, b4.y, acc[2][1]);
            acc[2][2] = fmaf(a2, b4.z, acc[2][2]);
            acc[2][3] = fmaf(a2, b4.w, acc[2][3]);
            acc[3][0] = fmaf(a3, b4.x, acc[3][0]);
            acc[3][1] = fmaf(a3, b4.y, acc[3][1]);
            acc[3][2] = fmaf(a3, b4.z, acc[3][2]);
            acc[3][3] = fmaf(a3, b4.w, acc[3][3]);
        }
        __syncthreads();
    }

    const int bb = m0 >> 10;
    const int tbase = m0 & 1023;
    #pragma unroll
    for (int r = 0; r < 4; r++) {
        int t = tbase + ty * 4 + r;
        #pragma unroll
        for (int c = 0; c < 4; c++) {
            int n = n0 + tx * 4 + c;
            int hh = n >> 7, e = n & 127;
            out[((size_t)(hh * B + bb) * T + t) * E + e] = acc[r][c];
        }
    }
}

// ---------------- head-gate softmax (unchanged) ------------------------------
__global__ void __launch_bounds__(128) sel_kernel(const float* __restrict__ x,
                                                  const float* __restrict__ w_s,
                                                  const float* __restrict__ b_s) {
    const int b = blockIdx.x;
    const int tid = threadIdx.x;
    __shared__ float mean_sh[128];
    __shared__ float logit_sh[8];

    const float* xb = x + (size_t)b * T * E;
    float s = 0.f;
    for (int t = 0; t < T; t++) s += xb[(size_t)t * E + tid];
    mean_sh[tid] = s * (1.0f / 1024.0f);
    __syncthreads();
    if (tid < H) {
        float l = b_s[tid];
        const float* wr = w_s + tid * E;
        #pragma unroll 4
        for (int e = 0; e < E; e++) l = fmaf(mean_sh[e], wr[e], l);
        logit_sh[tid] = l;
    }
    __syncthreads();
    if (tid == 0) {
        float mx = logit_sh[0];
        for (int h = 1; h < H; h++) mx = fmaxf(mx, logit_sh[h]);
        float ex[H]; float den = 0.f;
        for (int h = 0; h < H; h++) { ex[h] = expf(logit_sh[h] - mx); den += ex[h]; }
        float inv = 1.0f / den;
        for (int h = 0; h < H; h++) g_sel[b * H + h] = ex[h] * inv;
    }
}

// ---------------- cp.async helpers ------------------------------------------
__device__ __forceinline__ void cpa16(uint32_t dst, const void* src) {
    asm volatile("cp.async.cg.shared.global [%0], [%1], 16;\n" :: "r"(dst), "l"(src));
}
__device__ __forceinline__ void cpa_commit() {
    asm volatile("cp.async.commit_group;\n");
}
__device__ __forceinline__ void cpa_wait0() {
    asm volatile("cp.async.wait_group 0;\n");
}

// ---------------- q-tiled fused attention, 512 threads -----------------------
// smem: Kbuf[2][128][132] | s_sh[16][1024] | Qs[16][128] | mb[512] | misc
__global__ void __launch_bounds__(THR) attn3_kernel(const int* __restrict__ mask,
                                                    float* __restrict__ y) {
    extern __shared__ float sm[];
    float*    Kb0    = sm;                          // 33792 floats
    float*    s_sh   = sm + 2 * CH * KS;            // 16384
    float*    Qs     = s_sh + QT * 1024;            // 2048
    uint32_t* mb     = (uint32_t*)(Qs + QT * E);    // 512 words
    float*    tau_sh = (float*)(mb + 512);          // 16
    float*    sel_sh = tau_sh + 16;                 // 8
    int*      qscan  = (int*)(sel_sh + 8);          // 17
    int*      full_sh= qscan + 17;                  // 16
    int*      flat   = (int*)Kb0;                   // aliases K buffers (AV)

    const int b    = blockIdx.y;
    const int q0   = blockIdx.x * QT;
    const int tid  = threadIdx.x;
    const int krow = tid & 127;          // k-row within chunk / e in AV phase
    const int qh   = tid >> 7;           // 0..3 : q quartet
    const int wid  = tid >> 5;           // 0..15 : warp = q-row for sparsemax
    const int lane = tid & 31;

    float out_reg[4] = {0.f, 0.f, 0.f, 0.f};
    if (tid < H) sel_sh[tid] = g_sel[b * H + tid];

    // ---- mask bitwords (bit set = masked); one word per thread ----
    {
        int q = tid >> 5, wk = tid & 31;
        const int4* p = (const int4*)(mask + ((size_t)b * T + q0 + q) * T + wk * 32);
        uint32_t word = 0;
        #pragma unroll
        for (int i = 0; i < 8; i++) {
            int4 v = p[i];
            word |= (uint32_t)(v.x != 0) << (i * 4 + 0);
            word |= (uint32_t)(v.y != 0) << (i * 4 + 1);
            word |= (uint32_t)(v.z != 0) << (i * 4 + 2);
            word |= (uint32_t)(v.w != 0) << (i * 4 + 3);
        }
        mb[tid] = word;
    }
    __syncthreads();
    if (tid < QT) {
        int c = 0;
        #pragma unroll
        for (int i = 0; i < 32; i++) c += __popc(mb[tid * 32 + i]);
        full_sh[tid] = (c == 1024);
    }

    for (int h = 0; h < H; h++) {
        const size_t hb = (size_t)(h * B + b);
        const float* Kg = g_k + hb * T * E;

        // Q tile (16x128): one float4 per thread
        {
            int j = tid >> 5, c4 = tid & 31;
            ((float4*)Qs)[tid] =
                ((const float4*)(g_q + (hb * T + q0 + j) * E))[c4];
        }

        // prefetch chunk 0 (8 x 16B per thread)
        {
            const float4* src = (const float4*)Kg;
            uint32_t dbase = (uint32_t)__cvta_generic_to_shared(Kb0);
            #pragma unroll
            for (int i = 0; i < 8; i++) {
                int f = tid + i * THR;
                int r = f >> 5, c4 = f & 31;
                cpa16(dbase + (uint32_t)(r * KS + c4 * 4) * 4, src + f);
            }
            cpa_commit();
        }

        for (int c = 0; c < 8; c++) {
            cpa_wait0();
            __syncthreads();          // chunk c visible; buf[(c+1)&1] free
            if (c < 7) {              // prefetch next chunk (overlaps compute)
                const float4* src = (const float4*)(Kg + (size_t)(c + 1) * CH * E);
                float* dstb = Kb0 + ((c + 1) & 1) * (CH * KS);
                uint32_t dbase = (uint32_t)__cvta_generic_to_shared(dstb);
                #pragma unroll
                for (int i = 0; i < 8; i++) {
                    int f = tid + i * THR;
                    int r = f >> 5, c4 = f & 31;
                    cpa16(dbase + (uint32_t)(r * KS + c4 * 4) * 4, src + f);
                }
                cpa_commit();
            }

            // full-e dot: this thread = one k-row, 4 q accumulators
            const float* Kc = Kb0 + (c & 1) * (CH * KS) + krow * KS;
            float a0 = 0.f, a1 = 0.f, a2 = 0.f, a3 = 0.f;
            #pragma unroll
            for (int i = 0; i < 32; i++) {
                float4 kv = ((const float4*)Kc)[i];
                float4 v0 = *(const float4*)(Qs + (qh * 4 + 0) * 128 + i * 4);
                float4 v1 = *(const float4*)(Qs + (qh * 4 + 1) * 128 + i * 4);
                float4 v2 = *(const float4*)(Qs + (qh * 4 + 2) * 128 + i * 4);
                float4 v3 = *(const float4*)(Qs + (qh * 4 + 3) * 128 + i * 4);
                a0 = fmaf(kv.x, v0.x, fmaf(kv.y, v0.y, fmaf(kv.z, v0.z, fmaf(kv.w, v0.w, a0))));
                a1 = fmaf(kv.x, v1.x, fmaf(kv.y, v1.y, fmaf(kv.z, v1.z, fmaf(kv.w, v1.w, a1))));
                a2 = fmaf(kv.x, v2.x, fmaf(kv.y, v2.y, fmaf(kv.z, v2.z, fmaf(kv.w, v2.w, a2))));
                a3 = fmaf(kv.x, v3.x, fmaf(kv.y, v3.y, fmaf(kv.z, v3.z, fmaf(kv.w, v3.w, a3))));
            }
            const int kglob = c * CH + krow;
            const int wix = kglob >> 5, bix = kglob & 31;
            float r[4] = {a0, a1, a2, a3};
            #pragma unroll
            for (int j = 0; j < 4; j++) {
                int q = qh * 4 + j;
                uint32_t word = mb[q * 32 + wix];
                s_sh[q * 1024 + kglob] =
                    ((word >> bix) & 1u) ? NEGV : r[j] * SCALE;
            }
        }
        __syncthreads();              // all scores in s_sh

        // ---- sparsemax (Michelot), one warp per q-row ----
        float tau;
        int excl, cnt;
        {
            const float4* s4 = (const float4*)(s_sh + wid * 1024);
            if (full_sh[wid]) {
                tau = 3.0e38f;        // empty support -> zero row
            } else {
                tau = -1.0e8f;        // excludes NEGV, keeps all real scores
                int prev = -1;
                for (int it = 0; it < 64; it++) {
                    float ls = 0.f; int lc = 0;
                    #pragma unroll
                    for (int i = 0; i < 8; i++) {
                        float4 v = s4[lane + i * 32];
                        if (v.x > tau) { ls += v.x; lc++; }
                        if (v.y > tau) { ls += v.y; lc++; }
                        if (v.z > tau) { ls += v.z; lc++; }
                        if (v.w > tau) { ls += v.w; lc++; }
                    }
                    #pragma unroll
                    for (int o = 16; o; o >>= 1) {
                        ls += __shfl_xor_sync(0xffffffffu, ls, o);
                        lc += __shfl_xor_sync(0xffffffffu, lc, o);
                    }
                    if (lc == prev || lc == 0) break;
                    tau = (ls - 1.f) / (float)lc;
                    prev = lc;
                }
            }
            if (lane == 0) tau_sh[wid] = tau;

            cnt = 0;
            #pragma unroll
            for (int i = 0; i < 8; i++) {
                float4 v = s4[lane + i * 32];
                cnt += (v.x > tau) + (v.y > tau) + (v.z > tau) + (v.w > tau);
            }
            int incl = cnt;
            #pragma unroll
            for (int o = 1; o < 32; o <<= 1) {
                int t = __shfl_up_sync(0xffffffffu, incl, o);
                if (lane >= o) incl += t;
            }
            excl = incl - cnt;
            if (lane == 31) qscan[wid + 1] = incl;
        }
        __syncthreads();
        if (tid == 0) {
            qscan[0] = 0;
            #pragma unroll
            for (int i = 1; i <= 16; i++) qscan[i] += qscan[i - 1];
        }
        __syncthreads();

        // ---- flat support list (k indices, q-contiguous) ----
        if (cnt > 0) {
            int off = qscan[wid] + excl;
            const float4* s4 = (const float4*)(s_sh + wid * 1024);
            #pragma unroll
            for (int i = 0; i < 8; i++) {
                int kbase = (lane + i * 32) * 4;
                float4 v = s4[lane + i * 32];
                if (v.x > tau) flat[off++] = kbase;
                if (v.y > tau) flat[off++] = kbase + 1;
                if (v.z > tau) flat[off++] = kbase + 2;
                if (v.w > tau) flat[off++] = kbase + 3;
            }
        }
        __syncthreads();

        // ---- sparse AV: register accumulation, thread = (e, q quartet) ----
        {
            const float selh = sel_sh[h];
            const float* Vg = g_v + hb * T * E + krow;   // krow == e here
            #pragma unroll
            for (int j = 0; j < 4; j++) {
                int q = qh * 4 + j;
                float tq = tau_sh[q];
                int s = qscan[q], e = qscan[q + 1];
                const float* sq = s_sh + q * 1024;
                float a0 = 0.f, a1 = 0.f;
                int i = s;
                for (; i + 2 <= e; i += 2) {
                    int k0 = flat[i], k1 = flat[i + 1];
                    float p0 = sq[k0] - tq;
                    float p1 = sq[k1] - tq;
                    a0 = fmaf(p0, Vg[(size_t)k0 * E], a0);
                    a1 = fmaf(p1, Vg[(size_t)k1 * E], a1);
                }
                if (i < e) {
                    int k0 = flat[i];
                    a0 = fmaf(sq[k0] - tq, Vg[(size_t)k0 * E], a0);
                }
                out_reg[j] = fmaf(selh, a0 + a1, out_reg[j]);
            }
        }
        __syncthreads();   // flat (K buf) & s_sh reused next head
    }

    // ---- epilogue: direct global store, unique (q,e) per thread ----
    float* yb = y + ((size_t)b * T + q0) * E;
    #pragma unroll
    for (int j = 0; j < 4; j++)
        yb[(size_t)(qh * 4 + j) * E + krow] = out_reg[j];
}

// ---------------- launch -----------------------------------------------------
extern "C" void kernel_launch(void* const* d_in, const int* in_sizes, int n_in,
                              void* d_out, int out_size) {
    (void)in_sizes; (void)n_in; (void)out_size;
    const float* x    = (const float*)d_in[0];
    const int*   mask = (const int*)  d_in[1];
    const float* wq   = (const float*)d_in[2];
    const float* wk   = (const float*)d_in[3];
    const float* wv   = (const float*)d_in[4];
    const float* ws   = (const float*)d_in[5];
    const float* bs   = (const float*)d_in[6];
    float* y = (float*)d_out;

    const int smem_bytes = (2 * CH * KS + QT * 1024 + QT * E) * 4 + 2048 + 256;
    cudaFuncSetAttribute(attn3_kernel,
                         cudaFuncAttributeMaxDynamicSharedMemorySize, smem_bytes);

    dim3 gp(16, 128, 3);
    proj_kernel<<<gp, 256>>>(x, wq, wk, wv);
    sel_kernel<<<B, 128>>>(x, ws, bs);
    dim3 ga(T / QT, B);
    attn3_kernel<<<ga, THR, smem_bytes>>>(mask, y);
}

// round 9
// speedup vs baseline: 1.8326x; 1.8326x over previous
#include <cuda_runtime.h>
#include <cstdint>

#define B 8
#define T 1024
#define E 128
#define H 8
#define HB (H*B)
#define SCALE 0.08838834764831845f   // 1/sqrt(128)
#define NEGV (-1e9f)
#define QT 16
#define CH 128
#define KS 132                        // padded K row stride (floats)
#define QS 132                        // padded Q row stride (floats)
#define SS 1028                       // padded score row stride (floats)
#define THR 512

// ---------------- scratch (static device globals; no allocs allowed) --------
__device__ float g_q[HB * T * E];
__device__ float g_k[HB * T * E];
__device__ float g_v[HB * T * E];
__device__ float g_sel[B * H];

// ---------------- projection GEMM (unchanged) --------------------------------
__global__ void __launch_bounds__(256) proj_kernel(const float* __restrict__ x,
                                                   const float* __restrict__ wq,
                                                   const float* __restrict__ wk,
                                                   const float* __restrict__ wv) {
    const float* w;
    float* out;
    if (blockIdx.z == 0)      { w = wq; out = g_q; }
    else if (blockIdx.z == 1) { w = wk; out = g_k; }
    else                      { w = wv; out = g_v; }

    __shared__ float xs[64][68];
    __shared__ float ws[64][68];

    const int tid = threadIdx.x;
    const int m0 = blockIdx.y * 64;
    const int n0 = blockIdx.x * 64;
    const int ty = tid >> 4;
    const int tx = tid & 15;

    float acc[4][4];
    #pragma unroll
    for (int r = 0; r < 4; r++)
        #pragma unroll
        for (int c = 0; c < 4; c++) acc[r][c] = 0.f;

    for (int k0 = 0; k0 < 128; k0 += 64) {
        #pragma unroll
        for (int i = tid; i < 1024; i += 256) {
            int row = i >> 4, c4 = i & 15;
            *(float4*)&xs[row][c4 * 4] =
                *(const float4*)(x + (size_t)(m0 + row) * 128 + k0 + c4 * 4);
        }
        #pragma unroll
        for (int i = tid; i < 1024; i += 256) {
            int row = i >> 4, c4 = i & 15;
            *(float4*)&ws[row][c4 * 4] =
                *(const float4*)(w + (size_t)(k0 + row) * 1024 + n0 + c4 * 4);
        }
        __syncthreads();
        #pragma unroll
        for (int kk = 0; kk < 64; kk++) {
            float a0 = xs[ty * 4 + 0][kk];
            float a1 = xs[ty * 4 + 1][kk];
            float a2 = xs[ty * 4 + 2][kk];
            float a3 = xs[ty * 4 + 3][kk];
            float4 b4 = *(float4*)&ws[kk][tx * 4];
            acc[0][0] = fmaf(a0, b4.x, acc[0][0]);
            acc[0][1] = fmaf(a0, b4.y, acc[0][1]);
            acc[0][2] = fmaf(a0, b4.z, acc[0][2]);
            acc[0][3] = fmaf(a0, b4.w, acc[0][3]);
            acc[1][0] = fmaf(a1, b4.x, acc[1][0]);
            acc[1][1] = fmaf(a1, b4.y, acc[1][1]);
            acc[1][2] = fmaf(a1, b4.z, acc[1][2]);
            acc[1][3] = fmaf(a1, b4.w, acc[1][3]);
            acc[2][0] = fmaf(a2, b4.x, acc[2][0]);
            acc[2][1] = fmaf(a2, b4.y, acc[2][1]);
            acc[2][2] = fmaf(a2, b4.z, acc[2][2]);
            acc[2][3] = fmaf(a2, b4.w, acc[2][3]);
            acc[3][0] = fmaf(a3, b4.x, acc[3][0]);
            acc[3][1] = fmaf(a3, b4.y, acc[3][1]);
            acc[3][2] = fmaf(a3, b4.z, acc[3][2]);
            acc[3][3] = fmaf(a3, b4.w, acc[3][3]);
        }
        __syncthreads();
    }

    const int bb = m0 >> 10;
    const int tbase = m0 & 1023;
    #pragma unroll
    for (int r = 0; r < 4; r++) {
        int t = tbase + ty * 4 + r;
        #pragma unroll
        for (int c = 0; c < 4; c++) {
            int n = n0 + tx * 4 + c;
            int hh = n >> 7, e = n & 127;
            out[((size_t)(hh * B + bb) * T + t) * E + e] = acc[r][c];
        }
    }
}

// ---------------- head-gate softmax (unchanged) ------------------------------
__global__ void __launch_bounds__(128) sel_kernel(const float* __restrict__ x,
                                                  const float* __restrict__ w_s,
                                                  const float* __restrict__ b_s) {
    const int b = blockIdx.x;
    const int tid = threadIdx.x;
    __shared__ float mean_sh[128];
    __shared__ float logit_sh[8];

    const float* xb = x + (size_t)b * T * E;
    float s = 0.f;
    for (int t = 0; t < T; t++) s += xb[(size_t)t * E + tid];
    mean_sh[tid] = s * (1.0f / 1024.0f);
    __syncthreads();
    if (tid < H) {
        float l = b_s[tid];
        const float* wr = w_s + tid * E;
        #pragma unroll 4
        for (int e = 0; e < E; e++) l = fmaf(mean_sh[e], wr[e], l);
        logit_sh[tid] = l;
    }
    __syncthreads();
    if (tid == 0) {
        float mx = logit_sh[0];
        for (int h = 1; h < H; h++) mx = fmaxf(mx, logit_sh[h]);
        float ex[H]; float den = 0.f;
        for (int h = 0; h < H; h++) { ex[h] = expf(logit_sh[h] - mx); den += ex[h]; }
        float inv = 1.0f / den;
        for (int h = 0; h < H; h++) g_sel[b * H + h] = ex[h] * inv;
    }
}

// ---------------- helpers ----------------------------------------------------
__device__ __forceinline__ void cpa16(uint32_t dst, const void* src) {
    asm volatile("cp.async.cg.shared.global [%0], [%1], 16;\n" :: "r"(dst), "l"(src));
}
__device__ __forceinline__ void cpa_commit() {
    asm volatile("cp.async.commit_group;\n");
}
__device__ __forceinline__ void cpa_wait0() {
    asm volatile("cp.async.wait_group 0;\n");
}
__device__ __forceinline__ uint32_t tf32_rna(float x) {
    uint32_t r;
    asm("cvt.rna.tf32.f32 %0, %1;" : "=r"(r) : "f"(x));
    return r;
}
__device__ __forceinline__ void mma_tf32(float& c0, float& c1, float& c2, float& c3,
                                         uint32_t a0, uint32_t a1, uint32_t a2, uint32_t a3,
                                         uint32_t b0, uint32_t b1) {
    asm("mma.sync.aligned.m16n8k8.row.col.f32.tf32.tf32.f32 "
        "{%0,%1,%2,%3}, {%4,%5,%6,%7}, {%8,%9}, {%0,%1,%2,%3};"
        : "+f"(c0), "+f"(c1), "+f"(c2), "+f"(c3)
        : "r"(a0), "r"(a1), "r"(a2), "r"(a3), "r"(b0), "r"(b1));
}

// ---------------- q-tiled fused attention: 3xTF32 mma scores -----------------
__global__ void __launch_bounds__(THR) attn4_kernel(const int* __restrict__ mask,
                                                    float* __restrict__ y) {
    extern __shared__ float sm[];
    float*    Kb0    = sm;                          // 2*128*132 = 33792 floats
    float*    s_sh   = sm + 2 * CH * KS;            // 16*1028 = 16448
    float*    Qs     = s_sh + QT * SS;              // 16*132 = 2112
    uint32_t* mb     = (uint32_t*)(Qs + QT * QS);   // 512 words
    float*    tau_sh = (float*)(mb + 512);          // 16
    float*    sel_sh = tau_sh + 16;                 // 8
    int*      qscan  = (int*)(sel_sh + 8);          // 17
    int*      full_sh= qscan + 17;                  // 16
    int*      flat   = (int*)Kb0;                   // aliases K buffers (AV)

    const int b    = blockIdx.y;
    const int q0   = blockIdx.x * QT;
    const int tid  = threadIdx.x;
    const int krow = tid & 127;          // e in AV phase
    const int qh   = tid >> 7;           // 0..3 : q quartet (AV phase)
    const int wid  = tid >> 5;           // warp id: sparsemax row / mma warp
    const int lane = tid & 31;
    const int g    = lane >> 2;          // mma group row
    const int tig  = lane & 3;           // mma thread-in-group
    const int ks   = (wid & 7) * 16;     // k strip base (m)
    const int nq0  = (wid >> 3) * 8;     // q base (n)

    float out_reg[4] = {0.f, 0.f, 0.f, 0.f};
    if (tid < H) sel_sh[tid] = g_sel[b * H + tid];

    // ---- mask bitwords (bit set = masked); one word per thread ----
    {
        int q = tid >> 5, wk = tid & 31;
        const int4* p = (const int4*)(mask + ((size_t)b * T + q0 + q) * T + wk * 32);
        uint32_t word = 0;
        #pragma unroll
        for (int i = 0; i < 8; i++) {
            int4 v = p[i];
            word |= (uint32_t)(v.x != 0) << (i * 4 + 0);
            word |= (uint32_t)(v.y != 0) << (i * 4 + 1);
            word |= (uint32_t)(v.z != 0) << (i * 4 + 2);
            word |= (uint32_t)(v.w != 0) << (i * 4 + 3);
        }
        mb[tid] = word;
    }
    __syncthreads();
    if (tid < QT) {
        int c = 0;
        #pragma unroll
        for (int i = 0; i < 32; i++) c += __popc(mb[tid * 32 + i]);
        full_sh[tid] = (c == 1024);
    }

    for (int h = 0; h < H; h++) {
        const size_t hb = (size_t)(h * B + b);
        const float* Kg = g_k + hb * T * E;

        // Q tile (16x128) into padded Qs
        {
            int j = tid >> 5, c4 = tid & 31;
            *(float4*)(Qs + j * QS + c4 * 4) =
                ((const float4*)(g_q + (hb * T + q0 + j) * E))[c4];
        }

        // prefetch chunk 0
        {
            const float4* src = (const float4*)Kg;
            uint32_t dbase = (uint32_t)__cvta_generic_to_shared(Kb0);
            #pragma unroll
            for (int i = 0; i < 8; i++) {
                int f = tid + i * THR;
                int r = f >> 5, c4 = f & 31;
                cpa16(dbase + (uint32_t)(r * KS + c4 * 4) * 4, src + f);
            }
            cpa_commit();
        }

        for (int c = 0; c < 8; c++) {
            cpa_wait0();
            __syncthreads();          // chunk c visible; other buffer free
            if (c < 7) {              // prefetch next chunk (overlaps compute)
                const float4* src = (const float4*)(Kg + (size_t)(c + 1) * CH * E);
                float* dstb = Kb0 + ((c + 1) & 1) * (CH * KS);
                uint32_t dbase = (uint32_t)__cvta_generic_to_shared(dstb);
                #pragma unroll
                for (int i = 0; i < 8; i++) {
                    int f = tid + i * THR;
                    int r = f >> 5, c4 = f & 31;
                    cpa16(dbase + (uint32_t)(r * KS + c4 * 4) * 4, src + f);
                }
                cpa_commit();
            }

            // ---- 3xTF32 mma: S[128k x 16q] for this chunk ----
            const float* Kc = Kb0 + (c & 1) * (CH * KS);
            const float* Ar0 = Kc + (ks + g) * KS + tig;
            const float* Ar1 = Kc + (ks + g + 8) * KS + tig;
            const float* Br  = Qs + (nq0 + g) * QS + tig;
            float c0 = 0.f, c1 = 0.f, c2 = 0.f, c3 = 0.f;
            #pragma unroll
            for (int e0 = 0; e0 < 128; e0 += 8) {
                float a0f = Ar0[e0],     a2f = Ar0[e0 + 4];
                float a1f = Ar1[e0],     a3f = Ar1[e0 + 4];
                float b0f = Br[e0],      b1f = Br[e0 + 4];
                uint32_t ah0 = tf32_rna(a0f), ah1 = tf32_rna(a1f);
                uint32_t ah2 = tf32_rna(a2f), ah3 = tf32_rna(a3f);
                uint32_t bh0 = tf32_rna(b0f), bh1 = tf32_rna(b1f);
                uint32_t al0 = tf32_rna(a0f - __uint_as_float(ah0));
                uint32_t al1 = tf32_rna(a1f - __uint_as_float(ah1));
                uint32_t al2 = tf32_rna(a2f - __uint_as_float(ah2));
                uint32_t al3 = tf32_rna(a3f - __uint_as_float(ah3));
                uint32_t bl0 = tf32_rna(b0f - __uint_as_float(bh0));
                uint32_t bl1 = tf32_rna(b1f - __uint_as_float(bh1));
                mma_tf32(c0, c1, c2, c3, ah0, ah1, ah2, ah3, bl0, bl1); // hi*lo
                mma_tf32(c0, c1, c2, c3, al0, al1, al2, al3, bh0, bh1); // lo*hi
                mma_tf32(c0, c1, c2, c3, ah0, ah1, ah2, ah3, bh0, bh1); // hi*hi
            }

            // epilogue: mask + scale, write 4 scalars
            {
                const int kg0 = c * CH + ks + g;
                const int kg1 = kg0 + 8;
                const int qa  = nq0 + 2 * tig;
                const int qb  = qa + 1;
                uint32_t wa0 = mb[qa * 32 + (kg0 >> 5)];
                uint32_t wb0 = mb[qb * 32 + (kg0 >> 5)];
                uint32_t wa1 = mb[qa * 32 + (kg1 >> 5)];
                uint32_t wb1 = mb[qb * 32 + (kg1 >> 5)];
                s_sh[qa * SS + kg0] = ((wa0 >> (kg0 & 31)) & 1u) ? NEGV : c0 * SCALE;
                s_sh[qb * SS + kg0] = ((wb0 >> (kg0 & 31)) & 1u) ? NEGV : c1 * SCALE;
                s_sh[qa * SS + kg1] = ((wa1 >> (kg1 & 31)) & 1u) ? NEGV : c2 * SCALE;
                s_sh[qb * SS + kg1] = ((wb1 >> (kg1 & 31)) & 1u) ? NEGV : c3 * SCALE;
            }
        }
        __syncthreads();              // all scores in s_sh

        // ---- sparsemax (Michelot), one warp per q-row ----
        float tau;
        int excl, cnt;
        {
            const float4* s4 = (const float4*)(s_sh + wid * SS);
            if (full_sh[wid]) {
                tau = 3.0e38f;        // empty support -> zero row
            } else {
                tau = -1.0e8f;        // excludes NEGV, keeps all real scores
                int prev = -1;
                for (int it = 0; it < 64; it++) {
                    float ls = 0.f; int lc = 0;
                    #pragma unroll
                    for (int i = 0; i < 8; i++) {
                        float4 v = s4[lane + i * 32];
                        if (v.x > tau) { ls += v.x; lc++; }
                        if (v.y > tau) { ls += v.y; lc++; }
                        if (v.z > tau) { ls += v.z; lc++; }
                        if (v.w > tau) { ls += v.w; lc++; }
                    }
                    #pragma unroll
                    for (int o = 16; o; o >>= 1) {
                        ls += __shfl_xor_sync(0xffffffffu, ls, o);
                        lc += __shfl_xor_sync(0xffffffffu, lc, o);
                    }
                    if (lc == prev || lc == 0) break;
                    tau = (ls - 1.f) / (float)lc;
                    prev = lc;
                }
            }
            if (lane == 0) tau_sh[wid] = tau;

            cnt = 0;
            #pragma unroll
            for (int i = 0; i < 8; i++) {
                float4 v = s4[lane + i * 32];
                cnt += (v.x > tau) + (v.y > tau) + (v.z > tau) + (v.w > tau);
            }
            int incl = cnt;
            #pragma unroll
            for (int o = 1; o < 32; o <<= 1) {
                int t = __shfl_up_sync(0xffffffffu, incl, o);
                if (lane >= o) incl += t;
            }
            excl = incl - cnt;
            if (lane == 31) qscan[wid + 1] = incl;
        }
        __syncthreads();
        if (tid == 0) {
            qscan[0] = 0;
            #pragma unroll
            for (int i = 1; i <= 16; i++) qscan[i] += qscan[i - 1];
        }
        __syncthreads();

        // ---- flat support list (k indices, q-contiguous) ----
        if (cnt > 0) {
            int off = qscan[wid] + excl;
            const float4* s4 = (const float4*)(s_sh + wid * SS);
            #pragma unroll
            for (int i = 0; i < 8; i++) {
                int kbase = (lane + i * 32) * 4;
                float4 v = s4[lane + i * 32];
                if (v.x > tau) flat[off++] = kbase;
                if (v.y > tau) flat[off++] = kbase + 1;
                if (v.z > tau) flat[off++] = kbase + 2;
                if (v.w > tau) flat[off++] = kbase + 3;
            }
        }
        __syncthreads();

        // ---- sparse AV: register accumulation, thread = (e, q quartet) ----
        {
            const float selh = sel_sh[h];
            const float* Vg = g_v + hb * T * E + krow;   // krow == e here
            #pragma unroll
            for (int j = 0; j < 4; j++) {
                int q = qh * 4 + j;
                float tq = tau_sh[q];
                int s = qscan[q], e = qscan[q + 1];
                const float* sq = s_sh + q * SS;
                float a0 = 0.f, a1 = 0.f;
                int i = s;
                for (; i + 2 <= e; i += 2) {
                    int k0 = flat[i], k1 = flat[i + 1];
                    float p0 = sq[k0] - tq;
                    float p1 = sq[k1] - tq;
                    a0 = fmaf(p0, Vg[(size_t)k0 * E], a0);
                    a1 = fmaf(p1, Vg[(size_t)k1 * E], a1);
                }
                if (i < e) {
                    int k0 = flat[i];
                    a0 = fmaf(sq[k0] - tq, Vg[(size_t)k0 * E], a0);
                }
                out_reg[j] = fmaf(selh, a0 + a1, out_reg[j]);
            }
        }
        __syncthreads();   // flat (K buf) & s_sh reused next head
    }

    // ---- epilogue: direct global store, unique (q,e) per thread ----
    float* yb = y + ((size_t)b * T + q0) * E;
    #pragma unroll
    for (int j = 0; j < 4; j++)
        yb[(size_t)(qh * 4 + j) * E + krow] = out_reg[j];
}

// ---------------- launch -----------------------------------------------------
extern "C" void kernel_launch(void* const* d_in, const int* in_sizes, int n_in,
                              void* d_out, int out_size) {
    (void)in_sizes; (void)n_in; (void)out_size;
    const float* x    = (const float*)d_in[0];
    const int*   mask = (const int*)  d_in[1];
    const float* wq   = (const float*)d_in[2];
    const float* wk   = (const float*)d_in[3];
    const float* wv   = (const float*)d_in[4];
    const float* ws   = (const float*)d_in[5];
    const float* bs   = (const float*)d_in[6];
    float* y = (float*)d_out;

    const int smem_bytes = (2 * CH * KS + QT * SS + QT * QS) * 4 + 2048 + 256;
    cudaFuncSetAttribute(attn4_kernel,
                         cudaFuncAttributeMaxDynamicSharedMemorySize, smem_bytes);

    dim3 gp(16, 128, 3);
    proj_kernel<<<gp, 256>>>(x, wq, wk, wv);
    sel_kernel<<<B, 128>>>(x, ws, bs);
    dim3 ga(T / QT, B);
    attn4_kernel<<<ga, THR, smem_bytes>>>(mask, y);
}

// round 10
// speedup vs baseline: 2.1080x; 1.1503x over previous
#include <cuda_runtime.h>
#include <cstdint>

#define B 8
#define T 1024
#define E 128
#define H 8
#define HB (H*B)
#define SCALE 0.08838834764831845f   // 1/sqrt(128)
#define NEGV (-1e9f)
#define QT 16
#define CH 128
#define KS 132                        // padded K row stride (floats)
#define QS 132                        // padded Q row stride (floats)
#define SS 1028                       // padded score row stride (floats)
#define THR 512

// ---------------- scratch (static device globals; no allocs allowed) --------
__device__ float g_q[HB * T * E];
__device__ float g_k[HB * T * E];
__device__ float g_v[HB * T * E];
__device__ float g_sel[B * H];

// ---------------- projection GEMM (unchanged) --------------------------------
__global__ void __launch_bounds__(256) proj_kernel(const float* __restrict__ x,
                                                   const float* __restrict__ wq,
                                                   const float* __restrict__ wk,
                                                   const float* __restrict__ wv) {
    const float* w;
    float* out;
    if (blockIdx.z == 0)      { w = wq; out = g_q; }
    else if (blockIdx.z == 1) { w = wk; out = g_k; }
    else                      { w = wv; out = g_v; }

    __shared__ float xs[64][68];
    __shared__ float ws[64][68];

    const int tid = threadIdx.x;
    const int m0 = blockIdx.y * 64;
    const int n0 = blockIdx.x * 64;
    const int ty = tid >> 4;
    const int tx = tid & 15;

    float acc[4][4];
    #pragma unroll
    for (int r = 0; r < 4; r++)
        #pragma unroll
        for (int c = 0; c < 4; c++) acc[r][c] = 0.f;

    for (int k0 = 0; k0 < 128; k0 += 64) {
        #pragma unroll
        for (int i = tid; i < 1024; i += 256) {
            int row = i >> 4, c4 = i & 15;
            *(float4*)&xs[row][c4 * 4] =
                *(const float4*)(x + (size_t)(m0 + row) * 128 + k0 + c4 * 4);
        }
        #pragma unroll
        for (int i = tid; i < 1024; i += 256) {
            int row = i >> 4, c4 = i & 15;
            *(float4*)&ws[row][c4 * 4] =
                *(const float4*)(w + (size_t)(k0 + row) * 1024 + n0 + c4 * 4);
        }
        __syncthreads();
        #pragma unroll
        for (int kk = 0; kk < 64; kk++) {
            float a0 = xs[ty * 4 + 0][kk];
            float a1 = xs[ty * 4 + 1][kk];
            float a2 = xs[ty * 4 + 2][kk];
            float a3 = xs[ty * 4 + 3][kk];
            float4 b4 = *(float4*)&ws[kk][tx * 4];
            acc[0][0] = fmaf(a0, b4.x, acc[0][0]);
            acc[0][1] = fmaf(a0, b4.y, acc[0][1]);
            acc[0][2] = fmaf(a0, b4.z, acc[0][2]);
            acc[0][3] = fmaf(a0, b4.w, acc[0][3]);
            acc[1][0] = fmaf(a1, b4.x, acc[1][0]);
            acc[1][1] = fmaf(a1, b4.y, acc[1][1]);
            acc[1][2] = fmaf(a1, b4.z, acc[1][2]);
            acc[1][3] = fmaf(a1, b4.w, acc[1][3]);
            acc[2][0] = fmaf(a2, b4.x, acc[2][0]);
            acc[2][1] = fmaf(a2, b4.y, acc[2][1]);
            acc[2][2] = fmaf(a2, b4.z, acc[2][2]);
            acc[2][3] = fmaf(a2, b4.w, acc[2][3]);
            acc[3][0] = fmaf(a3, b4.x, acc[3][0]);
            acc[3][1] = fmaf(a3, b4.y, acc[3][1]);
            acc[3][2] = fmaf(a3, b4.z, acc[3][2]);
            acc[3][3] = fmaf(a3, b4.w, acc[3][3]);
        }
        __syncthreads();
    }

    const int bb = m0 >> 10;
    const int tbase = m0 & 1023;
    #pragma unroll
    for (int r = 0; r < 4; r++) {
        int t = tbase + ty * 4 + r;
        #pragma unroll
        for (int c = 0; c < 4; c++) {
            int n = n0 + tx * 4 + c;
            int hh = n >> 7, e = n & 127;
            out[((size_t)(hh * B + bb) * T + t) * E + e] = acc[r][c];
        }
    }
}

// ---------------- head-gate softmax (unchanged) ------------------------------
__global__ void __launch_bounds__(128) sel_kernel(const float* __restrict__ x,
                                                  const float* __restrict__ w_s,
                                                  const float* __restrict__ b_s) {
    const int b = blockIdx.x;
    const int tid = threadIdx.x;
    __shared__ float mean_sh[128];
    __shared__ float logit_sh[8];

    const float* xb = x + (size_t)b * T * E;
    float s = 0.f;
    for (int t = 0; t < T; t++) s += xb[(size_t)t * E + tid];
    mean_sh[tid] = s * (1.0f / 1024.0f);
    __syncthreads();
    if (tid < H) {
        float l = b_s[tid];
        const float* wr = w_s + tid * E;
        #pragma unroll 4
        for (int e = 0; e < E; e++) l = fmaf(mean_sh[e], wr[e], l);
        logit_sh[tid] = l;
    }
    __syncthreads();
    if (tid == 0) {
        float mx = logit_sh[0];
        for (int h = 1; h < H; h++) mx = fmaxf(mx, logit_sh[h]);
        float ex[H]; float den = 0.f;
        for (int h = 0; h < H; h++) { ex[h] = expf(logit_sh[h] - mx); den += ex[h]; }
        float inv = 1.0f / den;
        for (int h = 0; h < H; h++) g_sel[b * H + h] = ex[h] * inv;
    }
}

// ---------------- helpers ----------------------------------------------------
__device__ __forceinline__ void cpa16(uint32_t dst, const void* src) {
    asm volatile("cp.async.cg.shared.global [%0], [%1], 16;\n" :: "r"(dst), "l"(src));
}
__device__ __forceinline__ void cpa_commit() {
    asm volatile("cp.async.commit_group;\n");
}
__device__ __forceinline__ void cpa_wait0() {
    asm volatile("cp.async.wait_group 0;\n");
}
__device__ __forceinline__ uint32_t tf32_rna(float x) {
    uint32_t r;
    asm("cvt.rna.tf32.f32 %0, %1;" : "=r"(r) : "f"(x));
    return r;
}
__device__ __forceinline__ void mma_tf32(float& c0, float& c1, float& c2, float& c3,
                                         uint32_t a0, uint32_t a1, uint32_t a2, uint32_t a3,
                                         uint32_t b0, uint32_t b1) {
    asm("mma.sync.aligned.m16n8k8.row.col.f32.tf32.tf32.f32 "
        "{%0,%1,%2,%3}, {%4,%5,%6,%7}, {%8,%9}, {%0,%1,%2,%3};"
        : "+f"(c0), "+f"(c1), "+f"(c2), "+f"(c3)
        : "r"(a0), "r"(a1), "r"(a2), "r"(a3), "r"(b0), "r"(b1));
}

// ---------------- q-tiled fused attention: A=Q(hi/lo precomp), B=K ----------
__global__ void __launch_bounds__(THR) attn5_kernel(const int* __restrict__ mask,
                                                    float* __restrict__ y) {
    extern __shared__ float sm[];
    float*    Kb0    = sm;                          // 2*128*132 = 33792 floats
    float*    s_sh   = sm + 2 * CH * KS;            // 16*1028 = 16448
    float*    Qhi    = s_sh + QT * SS;              // 16*132 = 2112
    float*    Qlo    = Qhi + QT * QS;               // 2112
    uint32_t* mb     = (uint32_t*)(Qlo + QT * QS);  // 512 words
    float*    tau_sh = (float*)(mb + 512);          // 16
    float*    sel_sh = tau_sh + 16;                 // 8
    int*      qscan  = (int*)(sel_sh + 8);          // 17
    int*      full_sh= qscan + 17;                  // 16
    int*      flat   = (int*)Kb0;                   // aliases K buffers (AV)

    const int b    = blockIdx.y;
    const int q0   = blockIdx.x * QT;
    const int tid  = threadIdx.x;
    const int krow = tid & 127;          // e in AV phase
    const int qh   = tid >> 7;           // 0..3 : q quartet (AV phase)
    const int wid  = tid >> 5;           // warp id: sparsemax row / mma warp
    const int lane = tid & 31;
    const int g    = lane >> 2;          // mma group row (0..7)
    const int tig  = lane & 3;           // mma thread-in-group
    const int kb   = wid * 8;            // this warp's 8 k-rows within chunk

    float out_reg[4] = {0.f, 0.f, 0.f, 0.f};
    if (tid < H) sel_sh[tid] = g_sel[b * H + tid];

    // ---- mask bitwords (bit set = masked); one word per thread ----
    {
        int q = tid >> 5, wk = tid & 31;
        const int4* p = (const int4*)(mask + ((size_t)b * T + q0 + q) * T + wk * 32);
        uint32_t word = 0;
        #pragma unroll
        for (int i = 0; i < 8; i++) {
            int4 v = p[i];
            word |= (uint32_t)(v.x != 0) << (i * 4 + 0);
            word |= (uint32_t)(v.y != 0) << (i * 4 + 1);
            word |= (uint32_t)(v.z != 0) << (i * 4 + 2);
            word |= (uint32_t)(v.w != 0) << (i * 4 + 3);
        }
        mb[tid] = word;
    }
    __syncthreads();
    if (tid < QT) {
        int c = 0;
        #pragma unroll
        for (int i = 0; i < 32; i++) c += __popc(mb[tid * 32 + i]);
        full_sh[tid] = (c == 1024);
    }

    for (int h = 0; h < H; h++) {
        const size_t hb = (size_t)(h * B + b);
        const float* Kg = g_k + hb * T * E;

        // Q tile (16x128) -> tf32 hi/lo decomposition (once per head)
        {
            int j = tid >> 5, c4 = tid & 31;
            float4 qv = ((const float4*)(g_q + (hb * T + q0 + j) * E))[c4];
            float4 hi, lo;
            hi.x = __uint_as_float(tf32_rna(qv.x)); lo.x = __uint_as_float(tf32_rna(qv.x - hi.x));
            hi.y = __uint_as_float(tf32_rna(qv.y)); lo.y = __uint_as_float(tf32_rna(qv.y - hi.y));
            hi.z = __uint_as_float(tf32_rna(qv.z)); lo.z = __uint_as_float(tf32_rna(qv.z - hi.z));
            hi.w = __uint_as_float(tf32_rna(qv.w)); lo.w = __uint_as_float(tf32_rna(qv.w - hi.w));
            *(float4*)(Qhi + j * QS + c4 * 4) = hi;
            *(float4*)(Qlo + j * QS + c4 * 4) = lo;
        }

        // prefetch chunk 0
        {
            const float4* src = (const float4*)Kg;
            uint32_t dbase = (uint32_t)__cvta_generic_to_shared(Kb0);
            #pragma unroll
            for (int i = 0; i < 8; i++) {
                int f = tid + i * THR;
                int r = f >> 5, c4 = f & 31;
                cpa16(dbase + (uint32_t)(r * KS + c4 * 4) * 4, src + f);
            }
            cpa_commit();
        }

        for (int c = 0; c < 8; c++) {
            cpa_wait0();
            __syncthreads();          // chunk c visible; other buffer free; Qhi/Qlo ready
            if (c < 7) {              // prefetch next chunk (overlaps compute)
                const float4* src = (const float4*)(Kg + (size_t)(c + 1) * CH * E);
                float* dstb = Kb0 + ((c + 1) & 1) * (CH * KS);
                uint32_t dbase = (uint32_t)__cvta_generic_to_shared(dstb);
                #pragma unroll
                for (int i = 0; i < 8; i++) {
                    int f = tid + i * THR;
                    int r = f >> 5, c4 = f & 31;
                    cpa16(dbase + (uint32_t)(r * KS + c4 * 4) * 4, src + f);
                }
                cpa_commit();
            }

            // ---- 3xTF32 mma: A = Q (precomputed hi/lo), B = this warp's 8 K rows
            const float* Kc  = Kb0 + (c & 1) * (CH * KS);
            const float* Br  = Kc + (kb + g) * KS + tig;      // K row kb+g
            const float* Ah0 = Qhi + g * QS + tig;            // q row g
            const float* Ah1 = Qhi + (g + 8) * QS + tig;      // q row g+8
            const float* Al0 = Qlo + g * QS + tig;
            const float* Al1 = Qlo + (g + 8) * QS + tig;
            float c0 = 0.f, c1 = 0.f, c2 = 0.f, c3 = 0.f;
            #pragma unroll
            for (int e0 = 0; e0 < 128; e0 += 8) {
                uint32_t ah0 = __float_as_uint(Ah0[e0]);
                uint32_t ah1 = __float_as_uint(Ah1[e0]);
                uint32_t ah2 = __float_as_uint(Ah0[e0 + 4]);
                uint32_t ah3 = __float_as_uint(Ah1[e0 + 4]);
                uint32_t al0 = __float_as_uint(Al0[e0]);
                uint32_t al1 = __float_as_uint(Al1[e0]);
                uint32_t al2 = __float_as_uint(Al0[e0 + 4]);
                uint32_t al3 = __float_as_uint(Al1[e0 + 4]);
                float b0f = Br[e0], b1f = Br[e0 + 4];
                uint32_t bh0 = tf32_rna(b0f), bh1 = tf32_rna(b1f);
                uint32_t bl0 = tf32_rna(b0f - __uint_as_float(bh0));
                uint32_t bl1 = tf32_rna(b1f - __uint_as_float(bh1));
                mma_tf32(c0, c1, c2, c3, ah0, ah1, ah2, ah3, bl0, bl1); // hi*lo
                mma_tf32(c0, c1, c2, c3, al0, al1, al2, al3, bh0, bh1); // lo*hi
                mma_tf32(c0, c1, c2, c3, ah0, ah1, ah2, ah3, bh0, bh1); // hi*hi
            }

            // epilogue: C rows = q (g, g+8), cols = k (kb+2tig, +1); mask + scale
            {
                const int kg0 = c * CH + kb + 2 * tig;
                const int kg1 = kg0 + 1;
                const int qa  = g;
                const int qb  = g + 8;
                const int wix0 = kg0 >> 5, bix0 = kg0 & 31;
                const int wix1 = kg1 >> 5, bix1 = kg1 & 31;
                uint32_t wa0 = mb[qa * 32 + wix0];
                uint32_t wa1 = mb[qa * 32 + wix1];
                uint32_t wb0 = mb[qb * 32 + wix0];
                uint32_t wb1 = mb[qb * 32 + wix1];
                s_sh[qa * SS + kg0] = ((wa0 >> bix0) & 1u) ? NEGV : c0 * SCALE;
                s_sh[qa * SS + kg1] = ((wa1 >> bix1) & 1u) ? NEGV : c1 * SCALE;
                s_sh[qb * SS + kg0] = ((wb0 >> bix0) & 1u) ? NEGV : c2 * SCALE;
                s_sh[qb * SS + kg1] = ((wb1 >> bix1) & 1u) ? NEGV : c3 * SCALE;
            }
        }
        __syncthreads();              // all scores in s_sh

        // ---- sparsemax (Michelot), one warp per q-row ----
        float tau;
        int excl, cnt;
        {
            const float4* s4 = (const float4*)(s_sh + wid * SS);
            if (full_sh[wid]) {
                tau = 3.0e38f;        // empty support -> zero row
            } else {
                tau = -1.0e8f;        // excludes NEGV, keeps all real scores
                int prev = -1;
                for (int it = 0; it < 64; it++) {
                    float ls = 0.f; int lc = 0;
                    #pragma unroll
                    for (int i = 0; i < 8; i++) {
                        float4 v = s4[lane + i * 32];
                        if (v.x > tau) { ls += v.x; lc++; }
                        if (v.y > tau) { ls += v.y; lc++; }
                        if (v.z > tau) { ls += v.z; lc++; }
                        if (v.w > tau) { ls += v.w; lc++; }
                    }
                    #pragma unroll
                    for (int o = 16; o; o >>= 1) {
                        ls += __shfl_xor_sync(0xffffffffu, ls, o);
                        lc += __shfl_xor_sync(0xffffffffu, lc, o);
                    }
                    if (lc == prev || lc == 0) break;
                    tau = (ls - 1.f) / (float)lc;
                    prev = lc;
                }
            }
            if (lane == 0) tau_sh[wid] = tau;

            cnt = 0;
            #pragma unroll
            for (int i = 0; i < 8; i++) {
                float4 v = s4[lane + i * 32];
                cnt += (v.x > tau) + (v.y > tau) + (v.z > tau) + (v.w > tau);
            }
            int incl = cnt;
            #pragma unroll
            for (int o = 1; o < 32; o <<= 1) {
                int t = __shfl_up_sync(0xffffffffu, incl, o);
                if (lane >= o) incl += t;
            }
            excl = incl - cnt;
            if (lane == 31) qscan[wid + 1] = incl;
        }
        __syncthreads();
        if (tid == 0) {
            qscan[0] = 0;
            #pragma unroll
            for (int i = 1; i <= 16; i++) qscan[i] += qscan[i - 1];
        }
        __syncthreads();

        // ---- flat support list (k indices, q-contiguous) ----
        if (cnt > 0) {
            int off = qscan[wid] + excl;
            const float4* s4 = (const float4*)(s_sh + wid * SS);
            #pragma unroll
            for (int i = 0; i < 8; i++) {
                int kbase = (lane + i * 32) * 4;
                float4 v = s4[lane + i * 32];
                if (v.x > tau) flat[off++] = kbase;
                if (v.y > tau) flat[off++] = kbase + 1;
                if (v.z > tau) flat[off++] = kbase + 2;
                if (v.w > tau) flat[off++] = kbase + 3;
            }
        }
        __syncthreads();

        // ---- sparse AV: register accumulation, thread = (e, q quartet) ----
        {
            const float selh = sel_sh[h];
            const float* Vg = g_v + hb * T * E + krow;   // krow == e here
            #pragma unroll
            for (int j = 0; j < 4; j++) {
                int q = qh * 4 + j;
                float tq = tau_sh[q];
                int s = qscan[q], e = qscan[q + 1];
                const float* sq = s_sh + q * SS;
                float a0 = 0.f, a1 = 0.f;
                int i = s;
                for (; i + 2 <= e; i += 2) {
                    int k0 = flat[i], k1 = flat[i + 1];
                    float p0 = sq[k0] - tq;
                    float p1 = sq[k1] - tq;
                    a0 = fmaf(p0, Vg[(size_t)k0 * E], a0);
                    a1 = fmaf(p1, Vg[(size_t)k1 * E], a1);
                }
                if (i < e) {
                    int k0 = flat[i];
                    a0 = fmaf(sq[k0] - tq, Vg[(size_t)k0 * E], a0);
                }
                out_reg[j] = fmaf(selh, a0 + a1, out_reg[j]);
            }
        }
        __syncthreads();   // flat (K buf), s_sh, Qhi/Qlo reused next head
    }

    // ---- epilogue: direct global store, unique (q,e) per thread ----
    float* yb = y + ((size_t)b * T + q0) * E;
    #pragma unroll
    for (int j = 0; j < 4; j++)
        yb[(size_t)(qh * 4 + j) * E + krow] = out_reg[j];
}

// ---------------- launch -----------------------------------------------------
extern "C" void kernel_launch(void* const* d_in, const int* in_sizes, int n_in,
                              void* d_out, int out_size) {
    (void)in_sizes; (void)n_in; (void)out_size;
    const float* x    = (const float*)d_in[0];
    const int*   mask = (const int*)  d_in[1];
    const float* wq   = (const float*)d_in[2];
    const float* wk   = (const float*)d_in[3];
    const float* wv   = (const float*)d_in[4];
    const float* ws   = (const float*)d_in[5];
    const float* bs   = (const float*)d_in[6];
    float* y = (float*)d_out;

    const int smem_bytes = (2 * CH * KS + QT * SS + 2 * QT * QS) * 4 + 2048 + 256;
    cudaFuncSetAttribute(attn5_kernel,
                         cudaFuncAttributeMaxDynamicSharedMemorySize, smem_bytes);

    dim3 gp(16, 128, 3);
    proj_kernel<<<gp, 256>>>(x, wq, wk, wv);
    sel_kernel<<<B, 128>>>(x, ws, bs);
    dim3 ga(T / QT, B);
    attn5_kernel<<<ga, THR, smem_bytes>>>(mask, y);
}

// round 12
// speedup vs baseline: 2.1471x; 1.0185x over previous
#include <cuda_runtime.h>
#include <cstdint>

#define B 8
#define T 1024
#define E 128
#define H 8
#define HB (H*B)
#define SCALE 0.08838834764831845f   // 1/sqrt(128)
#define NEGV (-1e9f)
#define QT 16
#define CH 128
#define KS 132                        // padded K row stride (floats)
#define QS 132                        // padded Q row stride (floats)
#define SS 1028                       // padded score row stride (floats)
#define THR 512
#define PKS 132                       // proj x tile stride
#define PWS 68                        // proj wraw stride ([k][n] layout)

// ---------------- scratch (static device globals; no allocs allowed) --------
__device__ float g_q[HB * T * E];
__device__ float g_k[HB * T * E];
__device__ float g_v[HB * T * E];
__device__ float g_sel[B * H];

// ---------------- helpers ----------------------------------------------------
__device__ __forceinline__ void cpa16(uint32_t dst, const void* src) {
    asm volatile("cp.async.cg.shared.global [%0], [%1], 16;\n" :: "r"(dst), "l"(src));
}
__device__ __forceinline__ void cpa_commit() {
    asm volatile("cp.async.commit_group;\n");
}
__device__ __forceinline__ void cpa_wait0() {
    asm volatile("cp.async.wait_group 0;\n");
}
__device__ __forceinline__ uint32_t tf32_rna(float x) {
    uint32_t r;
    asm("cvt.rna.tf32.f32 %0, %1;" : "=r"(r) : "f"(x));
    return r;
}
__device__ __forceinline__ void mma_tf32(float& c0, float& c1, float& c2, float& c3,
                                         uint32_t a0, uint32_t a1, uint32_t a2, uint32_t a3,
                                         uint32_t b0, uint32_t b1) {
    asm("mma.sync.aligned.m16n8k8.row.col.f32.tf32.tf32.f32 "
        "{%0,%1,%2,%3}, {%4,%5,%6,%7}, {%8,%9}, {%0,%1,%2,%3};"
        : "+f"(c0), "+f"(c1), "+f"(c2), "+f"(c3)
        : "r"(a0), "r"(a1), "r"(a2), "r"(a3), "r"(b0), "r"(b1));
}

// ---------------- projection GEMM via 3xTF32 mma ------------------------------
// out[h][b][t][e] = sum_k x[(b,t)][k] * w[k][h*E+e]; tile 64m x 64n, K=128.
// 8 warps: (mw 0..3) x (nw 0..1); warp = m16 strip x 32 n (4 n8-tiles).
__global__ void __launch_bounds__(256) proj_mma_kernel(const float* __restrict__ x,
                                                       const float* __restrict__ wq,
                                                       const float* __restrict__ wk,
                                                       const float* __restrict__ wv) {
    const float* w;
    float* out;
    if (blockIdx.z == 0)      { w = wq; out = g_q; }
    else if (blockIdx.z == 1) { w = wk; out = g_k; }
    else                      { w = wv; out = g_v; }

    extern __shared__ float psm[];
    float* xs   = psm;                 // 64 * PKS = 8448 floats
    float* wraw = psm + 64 * PKS;      // 128 * PWS = 8704 floats ([k][n])

    const int tid  = threadIdx.x;
    const int wid  = tid >> 5;
    const int lane = tid & 31;
    const int mw   = wid >> 1;         // 0..3
    const int nw   = wid & 1;          // 0..1
    const int g    = lane >> 2;
    const int tig  = lane & 3;
    const int m0 = blockIdx.y * 64;
    const int n0 = blockIdx.x * 64;

    // stage x tile [64][128] (row-major, conflict-free STS.128)
    #pragma unroll
    for (int i = 0; i < 8; i++) {
        int f = tid + i * 256;                 // 0..2047 float4 units
        int row = f >> 5, c4 = f & 31;
        *(float4*)&xs[row * PKS + c4 * 4] =
            *(const float4*)(x + (size_t)(m0 + row) * 128 + c4 * 4);
    }
    // stage w tile as wraw[k][n] (n-contig rows; coalesced loads)
    #pragma unroll
    for (int i = 0; i < 8; i++) {
        int f = tid + i * 256;                 // 0..2047
        int k = f >> 4, c = f & 15;
        *(float4*)&wraw[k * PWS + c * 4] =
            *(const float4*)(w + (size_t)k * 1024 + n0 + c * 4);
    }
    __syncthreads();

    float c0[4], c1[4], c2[4], c3[4];
    #pragma unroll
    for (int t8 = 0; t8 < 4; t8++) { c0[t8] = c1[t8] = c2[t8] = c3[t8] = 0.f; }

    const float* Ar0 = xs + (mw * 16 + g) * PKS + tig;
    const float* Ar1 = xs + (mw * 16 + g + 8) * PKS + tig;
    const int nbase = nw * 32 + g;

    #pragma unroll
    for (int e0 = 0; e0 < 128; e0 += 8) {
        float a0f = Ar0[e0], a1f = Ar1[e0], a2f = Ar0[e0 + 4], a3f = Ar1[e0 + 4];
        uint32_t ah0 = tf32_rna(a0f), ah1 = tf32_rna(a1f);
        uint32_t ah2 = tf32_rna(a2f), ah3 = tf32_rna(a3f);
        uint32_t al0 = tf32_rna(a0f - __uint_as_float(ah0));
        uint32_t al1 = tf32_rna(a1f - __uint_as_float(ah1));
        uint32_t al2 = tf32_rna(a2f - __uint_as_float(ah2));
        uint32_t al3 = tf32_rna(a3f - __uint_as_float(ah3));
        const float* Wr0 = wraw + (tig + e0) * PWS + nbase;
        const float* Wr1 = wraw + (tig + 4 + e0) * PWS + nbase;
        #pragma unroll
        for (int t8 = 0; t8 < 4; t8++) {
            float b0f = Wr0[t8 * 8];
            float b1f = Wr1[t8 * 8];
            uint32_t bh0 = tf32_rna(b0f), bh1 = tf32_rna(b1f);
            uint32_t bl0 = tf32_rna(b0f - __uint_as_float(bh0));
            uint32_t bl1 = tf32_rna(b1f - __uint_as_float(bh1));
            mma_tf32(c0[t8], c1[t8], c2[t8], c3[t8], ah0, ah1, ah2, ah3, bl0, bl1);
            mma_tf32(c0[t8], c1[t8], c2[t8], c3[t8], al0, al1, al2, al3, bh0, bh1);
            mma_tf32(c0[t8], c1[t8], c2[t8], c3[t8], ah0, ah1, ah2, ah3, bh0, bh1);
        }
    }

    // epilogue: C rows = m (g, g+8), cols = n (2tig, 2tig+1); float2 stores
    const int bb = m0 >> 10;
    const int tbase = (m0 & 1023) + mw * 16;
    #pragma unroll
    for (int t8 = 0; t8 < 4; t8++) {
        int n = n0 + nw * 32 + t8 * 8 + 2 * tig;
        int hh = n >> 7, e = n & 127;
        float* o0 = out + ((size_t)(hh * B + bb) * T + tbase + g) * E + e;
        float* o1 = out + ((size_t)(hh * B + bb) * T + tbase + g + 8) * E + e;
        *(float2*)o0 = make_float2(c0[t8], c1[t8]);
        *(float2*)o1 = make_float2(c2[t8], c3[t8]);
    }
}

// ---------------- head-gate softmax (unchanged) ------------------------------
__global__ void __launch_bounds__(128) sel_kernel(const float* __restrict__ x,
                                                  const float* __restrict__ w_s,
                                                  const float* __restrict__ b_s) {
    const int b = blockIdx.x;
    const int tid = threadIdx.x;
    __shared__ float mean_sh[128];
    __shared__ float logit_sh[8];

    const float* xb = x + (size_t)b * T * E;
    float s = 0.f;
    for (int t = 0; t < T; t++) s += xb[(size_t)t * E + tid];
    mean_sh[tid] = s * (1.0f / 1024.0f);
    __syncthreads();
    if (tid < H) {
        float l = b_s[tid];
        const float* wr = w_s + tid * E;
        #pragma unroll 4
        for (int e = 0; e < E; e++) l = fmaf(mean_sh[e], wr[e], l);
        logit_sh[tid] = l;
    }
    __syncthreads();
    if (tid == 0) {
        float mx = logit_sh[0];
        for (int h = 1; h < H; h++) mx = fmaxf(mx, logit_sh[h]);
        float ex[H]; float den = 0.f;
        for (int h = 0; h < H; h++) { ex[h] = expf(logit_sh[h] - mx); den += ex[h]; }
        float inv = 1.0f / den;
        for (int h = 0; h < H; h++) g_sel[b * H + h] = ex[h] * inv;
    }
}

// ---------------- q-tiled fused attention: A=Q(hi/lo), B=K; reg Michelot ----
__global__ void __launch_bounds__(THR) attn6_kernel(const int* __restrict__ mask,
                                                    float* __restrict__ y) {
    extern __shared__ float sm[];
    float*    Kb0    = sm;                          // 2*128*132 = 33792 floats
    float*    s_sh   = sm + 2 * CH * KS;            // 16*1028 = 16448
    float*    Qhi    = s_sh + QT * SS;              // 16*132 = 2112
    float*    Qlo    = Qhi + QT * QS;               // 2112
    uint32_t* mb     = (uint32_t*)(Qlo + QT * QS);  // 512 words
    float*    tau_sh = (float*)(mb + 512);          // 16
    float*    sel_sh = tau_sh + 16;                 // 8
    int*      qscan  = (int*)(sel_sh + 8);          // 17
    int*      full_sh= qscan + 17;                  // 16
    int*      flat   = (int*)Kb0;                   // aliases K buffers (AV)

    const int b    = blockIdx.y;
    const int q0   = blockIdx.x * QT;
    const int tid  = threadIdx.x;
    const int krow = tid & 127;          // e in AV phase
    const int qh   = tid >> 7;           // 0..3 : q quartet (AV phase)
    const int wid  = tid >> 5;           // warp id: sparsemax row / mma warp
    const int lane = tid & 31;
    const int g    = lane >> 2;          // mma group row (0..7)
    const int tig  = lane & 3;           // mma thread-in-group
    const int kb   = wid * 8;            // this warp's 8 k-rows within chunk

    float out_reg[4] = {0.f, 0.f, 0.f, 0.f};
    if (tid < H) sel_sh[tid] = g_sel[b * H + tid];

    // ---- mask bitwords (bit set = masked); one word per thread ----
    {
        int q = tid >> 5, wk = tid & 31;
        const int4* p = (const int4*)(mask + ((size_t)b * T + q0 + q) * T + wk * 32);
        uint32_t word = 0;
        #pragma unroll
        for (int i = 0; i < 8; i++) {
            int4 v = p[i];
            word |= (uint32_t)(v.x != 0) << (i * 4 + 0);
            word |= (uint32_t)(v.y != 0) << (i * 4 + 1);
            word |= (uint32_t)(v.z != 0) << (i * 4 + 2);
            word |= (uint32_t)(v.w != 0) << (i * 4 + 3);
        }
        mb[tid] = word;
    }
    __syncthreads();
    if (tid < QT) {
        int c = 0;
        #pragma unroll
        for (int i = 0; i < 32; i++) c += __popc(mb[tid * 32 + i]);
        full_sh[tid] = (c == 1024);
    }

    for (int h = 0; h < H; h++) {
        const size_t hb = (size_t)(h * B + b);
        const float* Kg = g_k + hb * T * E;

        // Q tile (16x128) -> tf32 hi/lo decomposition (once per head)
        {
            int j = tid >> 5, c4 = tid & 31;
            float4 qv = ((const float4*)(g_q + (hb * T + q0 + j) * E))[c4];
            float4 hi, lo;
            hi.x = __uint_as_float(tf32_rna(qv.x)); lo.x = __uint_as_float(tf32_rna(qv.x - hi.x));
            hi.y = __uint_as_float(tf32_rna(qv.y)); lo.y = __uint_as_float(tf32_rna(qv.y - hi.y));
            hi.z = __uint_as_float(tf32_rna(qv.z)); lo.z = __uint_as_float(tf32_rna(qv.z - hi.z));
            hi.w = __uint_as_float(tf32_rna(qv.w)); lo.w = __uint_as_float(tf32_rna(qv.w - hi.w));
            *(float4*)(Qhi + j * QS + c4 * 4) = hi;
            *(float4*)(Qlo + j * QS + c4 * 4) = lo;
        }

        // prefetch chunk 0
        {
            const float4* src = (const float4*)Kg;
            uint32_t dbase = (uint32_t)__cvta_generic_to_shared(Kb0);
            #pragma unroll
            for (int i = 0; i < 8; i++) {
                int f = tid + i * THR;
                int r = f >> 5, c4 = f & 31;
                cpa16(dbase + (uint32_t)(r * KS + c4 * 4) * 4, src + f);
            }
            cpa_commit();
        }

        for (int c = 0; c < 8; c++) {
            cpa_wait0();
            __syncthreads();          // chunk c visible; other buffer free; Qhi/Qlo ready
            if (c < 7) {              // prefetch next chunk (overlaps compute)
                const float4* src = (const float4*)(Kg + (size_t)(c + 1) * CH * E);
                float* dstb = Kb0 + ((c + 1) & 1) * (CH * KS);
                uint32_t dbase = (uint32_t)__cvta_generic_to_shared(dstb);
                #pragma unroll
                for (int i = 0; i < 8; i++) {
                    int f = tid + i * THR;
                    int r = f >> 5, c4 = f & 31;
                    cpa16(dbase + (uint32_t)(r * KS + c4 * 4) * 4, src + f);
                }
                cpa_commit();
            }

            // ---- 3xTF32 mma: A = Q (precomputed hi/lo), B = this warp's 8 K rows
            const float* Kc  = Kb0 + (c & 1) * (CH * KS);
            const float* Br  = Kc + (kb + g) * KS + tig;
            const float* Ah0 = Qhi + g * QS + tig;
            const float* Ah1 = Qhi + (g + 8) * QS + tig;
            const float* Al0 = Qlo + g * QS + tig;
            const float* Al1 = Qlo + (g + 8) * QS + tig;
            float c0 = 0.f, c1 = 0.f, c2 = 0.f, c3 = 0.f;
            #pragma unroll
            for (int e0 = 0; e0 < 128; e0 += 8) {
                uint32_t ah0 = __float_as_uint(Ah0[e0]);
                uint32_t ah1 = __float_as_uint(Ah1[e0]);
                uint32_t ah2 = __float_as_uint(Ah0[e0 + 4]);
                uint32_t ah3 = __float_as_uint(Ah1[e0 + 4]);
                uint32_t al0 = __float_as_uint(Al0[e0]);
                uint32_t al1 = __float_as_uint(Al1[e0]);
                uint32_t al2 = __float_as_uint(Al0[e0 + 4]);
                uint32_t al3 = __float_as_uint(Al1[e0 + 4]);
                float b0f = Br[e0], b1f = Br[e0 + 4];
                uint32_t bh0 = tf32_rna(b0f), bh1 = tf32_rna(b1f);
                uint32_t bl0 = tf32_rna(b0f - __uint_as_float(bh0));
                uint32_t bl1 = tf32_rna(b1f - __uint_as_float(bh1));
                mma_tf32(c0, c1, c2, c3, ah0, ah1, ah2, ah3, bl0, bl1); // hi*lo
                mma_tf32(c0, c1, c2, c3, al0, al1, al2, al3, bh0, bh1); // lo*hi
                mma_tf32(c0, c1, c2, c3, ah0, ah1, ah2, ah3, bh0, bh1); // hi*hi
            }

            // epilogue: C rows = q (g, g+8), cols = k (kb+2tig, +1); mask + scale
            {
                const int kg0 = c * CH + kb + 2 * tig;
                const int kg1 = kg0 + 1;
                const int qa  = g;
                const int qb  = g + 8;
                const int wix0 = kg0 >> 5, bix0 = kg0 & 31;
                const int wix1 = kg1 >> 5, bix1 = kg1 & 31;
                uint32_t wa0 = mb[qa * 32 + wix0];
                uint32_t wa1 = mb[qa * 32 + wix1];
                uint32_t wb0 = mb[qb * 32 + wix0];
                uint32_t wb1 = mb[qb * 32 + wix1];
                s_sh[qa * SS + kg0] = ((wa0 >> bix0) & 1u) ? NEGV : c0 * SCALE;
                s_sh[qa * SS + kg1] = ((wa1 >> bix1) & 1u) ? NEGV : c1 * SCALE;
                s_sh[qb * SS + kg0] = ((wb0 >> bix0) & 1u) ? NEGV : c2 * SCALE;
                s_sh[qb * SS + kg1] = ((wb1 >> bix1) & 1u) ? NEGV : c3 * SCALE;
            }
        }
        __syncthreads();              // all scores in s_sh

        // ---- load this warp's score row into registers (one pass) ----
        float4 vr[8];
        {
            const float4* s4 = (const float4*)(s_sh + wid * SS);
            #pragma unroll
            for (int i = 0; i < 8; i++) vr[i] = s4[lane + i * 32];
        }

        // ---- sparsemax (Michelot), one warp per q-row, register-resident ----
        float tau;
        int excl, cnt;
        {
            if (full_sh[wid]) {
                tau = 3.0e38f;        // empty support -> zero row
            } else {
                tau = -1.0e8f;        // excludes NEGV, keeps all real scores
                int prev = -1;
                for (int it = 0; it < 64; it++) {
                    float ls = 0.f; int lc = 0;
                    #pragma unroll
                    for (int i = 0; i < 8; i++) {
                        float4 v = vr[i];
                        if (v.x > tau) { ls += v.x; lc++; }
                        if (v.y > tau) { ls += v.y; lc++; }
                        if (v.z > tau) { ls += v.z; lc++; }
                        if (v.w > tau) { ls += v.w; lc++; }
                    }
                    #pragma unroll
                    for (int o = 16; o; o >>= 1) {
                        ls += __shfl_xor_sync(0xffffffffu, ls, o);
                        lc += __shfl_xor_sync(0xffffffffu, lc, o);
                    }
                    if (lc == prev || lc == 0) break;
                    tau = (ls - 1.f) / (float)lc;
                    prev = lc;
                }
            }
            if (lane == 0) tau_sh[wid] = tau;

            cnt = 0;
            #pragma unroll
            for (int i = 0; i < 8; i++) {
                float4 v = vr[i];
                cnt += (v.x > tau) + (v.y > tau) + (v.z > tau) + (v.w > tau);
            }
            int incl = cnt;
            #pragma unroll
            for (int o = 1; o < 32; o <<= 1) {
                int t = __shfl_up_sync(0xffffffffu, incl, o);
                if (lane >= o) incl += t;
            }
            excl = incl - cnt;
            if (lane == 31) qscan[wid + 1] = incl;
        }
        __syncthreads();
        if (tid == 0) {
            qscan[0] = 0;
            #pragma unroll
            for (int i = 1; i <= 16; i++) qscan[i] += qscan[i - 1];
        }
        __syncthreads();

        // ---- flat support list (k indices, q-contiguous), from registers ----
        if (cnt > 0) {
            int off = qscan[wid] + excl;
            #pragma unroll
            for (int i = 0; i < 8; i++) {
                int kbase = (lane + i * 32) * 4;
                float4 v = vr[i];
                if (v.x > tau) flat[off++] = kbase;
                if (v.y > tau) flat[off++] = kbase + 1;
                if (v.z > tau) flat[off++] = kbase + 2;
                if (v.w > tau) flat[off++] = kbase + 3;
            }
        }
        __syncthreads();

        // ---- sparse AV: register accumulation, thread = (e, q quartet) ----
        {
            const float selh = sel_sh[h];
            const float* Vg = g_v + hb * T * E + krow;   // krow == e here
            #pragma unroll
            for (int j = 0; j < 4; j++) {
                int q = qh * 4 + j;
                float tq = tau_sh[q];
                int s = qscan[q], e = qscan[q + 1];
                const float* sq = s_sh + q * SS;
                float a0 = 0.f, a1 = 0.f;
                int i = s;
                for (; i + 2 <= e; i += 2) {
                    int k0 = flat[i], k1 = flat[i + 1];
                    float p0 = sq[k0] - tq;
                    float p1 = sq[k1] - tq;
                    a0 = fmaf(p0, Vg[(size_t)k0 * E], a0);
                    a1 = fmaf(p1, Vg[(size_t)k1 * E], a1);
                }
                if (i < e) {
                    int k0 = flat[i];
                    a0 = fmaf(sq[k0] - tq, Vg[(size_t)k0 * E], a0);
                }
                out_reg[j] = fmaf(selh, a0 + a1, out_reg[j]);
            }
        }
        __syncthreads();   // flat (K buf), s_sh, Qhi/Qlo reused next head
    }

    // ---- epilogue: direct global store, unique (q,e) per thread ----
    float* yb = y + ((size_t)b * T + q0) * E;
    #pragma unroll
    for (int j = 0; j < 4; j++)
        yb[(size_t)(qh * 4 + j) * E + krow] = out_reg[j];
}

// ---------------- launch -----------------------------------------------------
extern "C" void kernel_launch(void* const* d_in, const int* in_sizes, int n_in,
                              void* d_out, int out_size) {
    (void)in_sizes; (void)n_in; (void)out_size;
    const float* x    = (const float*)d_in[0];
    const int*   mask = (const int*)  d_in[1];
    const float* wq   = (const float*)d_in[2];
    const float* wk   = (const float*)d_in[3];
    const float* wv   = (const float*)d_in[4];
    const float* ws   = (const float*)d_in[5];
    const float* bs   = (const float*)d_in[6];
    float* y = (float*)d_out;

    const int proj_smem = (64 * PKS + 128 * PWS) * 4;   // 68608 B
    cudaFuncSetAttribute(proj_mma_kernel,
                         cudaFuncAttributeMaxDynamicSharedMemorySize, proj_smem);
    const int smem_bytes = (2 * CH * KS + QT * SS + 2 * QT * QS) * 4 + 2048 + 256;
    cudaFuncSetAttribute(attn6_kernel,
                         cudaFuncAttributeMaxDynamicSharedMemorySize, smem_bytes);

    dim3 gp(16, 128, 3);
    proj_mma_kernel<<<gp, 256, proj_smem>>>(x, wq, wk, wv);
    sel_kernel<<<B, 128>>>(x, ws, bs);
    dim3 ga(T / QT, B);
    attn6_kernel<<<ga, THR, smem_bytes>>>(mask, y);
}